// round 9
// baseline (speedup 1.0000x reference)
#include <cuda_runtime.h>
#include <cuda_bf16.h>

#define NPIX (8*128*128)   // 131072 pixels
#define CCH  64

// Scratch (device globals). Activations NHWC.
__device__ __nv_bfloat16 g_hb0[(size_t)NPIX*CCH];
__device__ __nv_bfloat16 g_hb1[(size_t)NPIX*CCH];
__device__ float g_q[(size_t)NPIX*CCH];
__device__ __nv_bfloat16 g_kb[(size_t)NPIX*CCH];
__device__ __nv_bfloat16 g_vb[(size_t)NPIX*CCH];
__device__ __nv_bfloat16 g_wb[3*192*64];   // pre-converted [w1;w2;w3], k contiguous

__device__ __forceinline__ unsigned pack_bf(float a, float b) {
    __nv_bfloat162 h = __floats2bfloat162_rn(a, b);
    return *reinterpret_cast<unsigned*>(&h);
}
__device__ __forceinline__ void cp16(unsigned smem_dst, const void* gsrc) {
    asm volatile("cp.async.ca.shared.global [%0], [%1], 16;\n"
                 :: "r"(smem_dst), "l"(gsrc));
}
__device__ __forceinline__ float bflo(unsigned u) { return __uint_as_float(u << 16); }
__device__ __forceinline__ float bfhi(unsigned u) { return __uint_as_float(u & 0xffff0000u); }
__device__ __forceinline__ void tf32_split(float x, unsigned& hi, unsigned& lo) {
    unsigned h;
    asm("cvt.rna.tf32.f32 %0, %1;" : "=r"(h) : "f"(x));
    float hf = __uint_as_float(h);
    asm("cvt.rna.tf32.f32 %0, %1;" : "=r"(lo) : "f"(x - hf));
    hi = h;
}
__device__ __forceinline__ unsigned bf2tf(__nv_bfloat16 v) {
    return __float_as_uint(__bfloat162float(v));   // exact in tf32
}

#define MMA(c, a0,a1,a2,a3, b0,b1) \
    asm volatile("mma.sync.aligned.m16n8k16.row.col.f32.bf16.bf16.f32 " \
                 "{%0,%1,%2,%3}, {%4,%5,%6,%7}, {%8,%9}, {%0,%1,%2,%3};" \
                 : "+f"(c[0]), "+f"(c[1]), "+f"(c[2]), "+f"(c[3]) \
                 : "r"(a0), "r"(a1), "r"(a2), "r"(a3), "r"(b0), "r"(b1))
#define MMAT(c, a0,a1,a2,a3, b0,b1) \
    asm volatile("mma.sync.aligned.m16n8k8.row.col.f32.tf32.tf32.f32 " \
                 "{%0,%1,%2,%3}, {%4,%5,%6,%7}, {%8,%9}, {%0,%1,%2,%3};" \
                 : "+f"(c[0]), "+f"(c[1]), "+f"(c[2]), "+f"(c[3]) \
                 : "r"(a0), "r"(a1), "r"(a2), "r"(a3), "r"(b0), "r"(b1))

// ---------------------------------------------------------------------------
// weight convert: [64x64] fp32 x3 -> bf16 [192][64]
// ---------------------------------------------------------------------------
__global__ void convert_w_k(const float* __restrict__ w1, const float* __restrict__ w2,
                            const float* __restrict__ w3, __nv_bfloat16* __restrict__ dst) {
    int idx = blockIdx.x*256 + threadIdx.x;
    if (idx >= 192*64) return;
    float v = (idx < 4096) ? w1[idx] : (idx < 8192) ? w2[idx-4096] : w3[idx-8192];
    dst[idx] = __float2bfloat16(v);
}

// ---------------------------------------------------------------------------
// conv_in: x NCHW -> relu(conv3x3) -> NHWC bf16. 16x16 tile, halo smem,
// weights transposed [tap][o] for vectorized broadcast reads.
// ---------------------------------------------------------------------------
__global__ __launch_bounds__(256) void conv_in_k(const float* __restrict__ x,
                                                 const float* __restrict__ w,
                                                 __nv_bfloat16* __restrict__ out) {
    __shared__ float ws2[27*64];           // [tap][o]
    __shared__ float xs[3][18][18];
    int tid = threadIdx.x;
    int bx = blockIdx.x, by = blockIdx.y, n = blockIdx.z;
    int y0 = by*16, x0 = bx*16;

    for (int idx = tid; idx < 1728; idx += 256) {
        int o = idx / 27, t = idx % 27;
        ws2[t*64 + o] = w[idx];
    }
    for (int idx = tid; idx < 972; idx += 256) {
        int c = idx / 324, r = idx % 324;
        int yy = y0 + r/18 - 1, xx = x0 + r%18 - 1;
        float v = 0.f;
        if (yy >= 0 && yy < 128 && xx >= 0 && xx < 128)
            v = x[((n*3 + c) << 14) + (yy << 7) + xx];
        xs[c][r/18][r%18] = v;
    }
    __syncthreads();

    int py = tid >> 4, px = tid & 15;
    float v[27];
    int t = 0;
    #pragma unroll
    for (int c = 0; c < 3; c++)
        #pragma unroll
        for (int dy = 0; dy < 3; dy++)
            #pragma unroll
            for (int dx = 0; dx < 3; dx++, t++)
                v[t] = xs[c][py+dy][px+dx];

    size_t obase = (((size_t)n << 14) + ((size_t)(y0+py) << 7) + (x0+px)) * 64;
    #pragma unroll
    for (int ch = 0; ch < 4; ch++) {
        float acc[16];
        #pragma unroll
        for (int j = 0; j < 16; j++) acc[j] = 0.f;
        #pragma unroll
        for (int tt = 0; tt < 27; tt++) {
            float xv = v[tt];
            const float4* wp = (const float4*)(ws2 + tt*64 + ch*16);
            float4 w0 = wp[0], w1 = wp[1], w2 = wp[2], w3 = wp[3];
            acc[0]  = fmaf(xv, w0.x, acc[0]);  acc[1]  = fmaf(xv, w0.y, acc[1]);
            acc[2]  = fmaf(xv, w0.z, acc[2]);  acc[3]  = fmaf(xv, w0.w, acc[3]);
            acc[4]  = fmaf(xv, w1.x, acc[4]);  acc[5]  = fmaf(xv, w1.y, acc[5]);
            acc[6]  = fmaf(xv, w1.z, acc[6]);  acc[7]  = fmaf(xv, w1.w, acc[7]);
            acc[8]  = fmaf(xv, w2.x, acc[8]);  acc[9]  = fmaf(xv, w2.y, acc[9]);
            acc[10] = fmaf(xv, w2.z, acc[10]); acc[11] = fmaf(xv, w2.w, acc[11]);
            acc[12] = fmaf(xv, w3.x, acc[12]); acc[13] = fmaf(xv, w3.y, acc[13]);
            acc[14] = fmaf(xv, w3.z, acc[14]); acc[15] = fmaf(xv, w3.w, acc[15]);
        }
        uint4 u0 = make_uint4(pack_bf(fmaxf(acc[0],0.f),  fmaxf(acc[1],0.f)),
                              pack_bf(fmaxf(acc[2],0.f),  fmaxf(acc[3],0.f)),
                              pack_bf(fmaxf(acc[4],0.f),  fmaxf(acc[5],0.f)),
                              pack_bf(fmaxf(acc[6],0.f),  fmaxf(acc[7],0.f)));
        uint4 u1 = make_uint4(pack_bf(fmaxf(acc[8],0.f),  fmaxf(acc[9],0.f)),
                              pack_bf(fmaxf(acc[10],0.f), fmaxf(acc[11],0.f)),
                              pack_bf(fmaxf(acc[12],0.f), fmaxf(acc[13],0.f)),
                              pack_bf(fmaxf(acc[14],0.f), fmaxf(acc[15],0.f)));
        ((uint4*)(out + obase + ch*16))[0] = u0;
        ((uint4*)(out + obase + ch*16))[1] = u1;
    }
}

// ---------------------------------------------------------------------------
// qkv: fused triple 1x1 via bf16 mma (unchanged from passing round 8)
// ---------------------------------------------------------------------------
__global__ __launch_bounds__(256) void qkv_k(const __nv_bfloat16* __restrict__ in,
                                             const __nv_bfloat16* __restrict__ wb,
                                             float* __restrict__ qo,
                                             __nv_bfloat16* __restrict__ ko,
                                             __nv_bfloat16* __restrict__ vo) {
    __shared__ __nv_bfloat16 a_s[64*72];
    __shared__ __nv_bfloat16 w_s[192*72];
    int tid = threadIdx.x;
    size_t pix0 = (size_t)blockIdx.x * 64;

    unsigned a_base = (unsigned)__cvta_generic_to_shared(a_s);
    unsigned w_base = (unsigned)__cvta_generic_to_shared(w_s);

    #pragma unroll
    for (int i = 0; i < 2; i++) {
        int idx = tid + 256*i;
        int row = idx >> 3, c8 = idx & 7;
        cp16(a_base + row*144 + c8*16, in + pix0*64 + (size_t)idx*8);
    }
    #pragma unroll
    for (int i = 0; i < 6; i++) {
        int idx = tid + 256*i;
        int row = idx >> 3, c8 = idx & 7;
        cp16(w_base + row*144 + c8*16, wb + row*64 + c8*8);
    }
    asm volatile("cp.async.commit_group;\n" ::: "memory");
    asm volatile("cp.async.wait_group 0;\n" ::: "memory");
    __syncthreads();

    int lane = tid & 31, w = tid >> 5;
    int wm = (w >> 1) * 16;
    int wn = (w & 1) * 96;
    int lr = lane >> 2, lc = lane & 3;

    float c[12][4];
    #pragma unroll
    for (int t = 0; t < 12; t++)
        #pragma unroll
        for (int i = 0; i < 4; i++) c[t][i] = 0.f;

    #pragma unroll
    for (int ks = 0; ks < 4; ks++) {
        int k0 = ks*16;
        unsigned a0 = *(const unsigned*)&a_s[(wm+lr  )*72 + k0 + lc*2    ];
        unsigned a1 = *(const unsigned*)&a_s[(wm+lr+8)*72 + k0 + lc*2    ];
        unsigned a2 = *(const unsigned*)&a_s[(wm+lr  )*72 + k0 + lc*2 + 8];
        unsigned a3 = *(const unsigned*)&a_s[(wm+lr+8)*72 + k0 + lc*2 + 8];
        #pragma unroll
        for (int t = 0; t < 12; t++) {
            int bc = wn + t*8 + lr;
            unsigned b0 = *(const unsigned*)&w_s[bc*72 + k0 + lc*2    ];
            unsigned b1 = *(const unsigned*)&w_s[bc*72 + k0 + lc*2 + 8];
            MMA(c[t], a0,a1,a2,a3, b0,b1);
        }
    }

    size_t pixA = pix0 + wm + lr;
    size_t pixB = pixA + 8;
    #pragma unroll
    for (int t = 0; t < 12; t++) {
        int n0 = wn + t*8 + lc*2;
        if (n0 < 64) {
            *(float2*)(qo + pixA*64 + n0) = make_float2(c[t][0], c[t][1]);
            *(float2*)(qo + pixB*64 + n0) = make_float2(c[t][2], c[t][3]);
        } else if (n0 < 128) {
            *(unsigned*)(ko + pixA*64 + n0 - 64) = pack_bf(c[t][0], c[t][1]);
            *(unsigned*)(ko + pixB*64 + n0 - 64) = pack_bf(c[t][2], c[t][3]);
        } else {
            *(unsigned*)(vo + pixA*64 + n0 - 128) = pack_bf(c[t][0], c[t][1]);
            *(unsigned*)(vo + pixB*64 + n0 - 128) = pack_bf(c[t][2], c[t][3]);
        }
    }
}

// ---------------------------------------------------------------------------
// attn via tensor cores: per 8x8 tile, S = Q K^T (tf32 hi/lo), fp32 softmax
// in place, O = P V (tf32 hi/lo), relu, bf16 out. K/V from global (qkv_k),
// V used untransposed ([hp][ch]) via direct B-fragment scalar reads.
// ---------------------------------------------------------------------------
#define QSP 68     // fp32 row stride: q
#define KSP 72     // bf16 row stride: k_s, v_s
#define SSP 148    // fp32 row stride: S/P
// smem: q_s [0,17408) | k_s [17408,38144) | v_s [38144,58880)
//       S/P fp32 64x148 overlays [0,37888) after stage A
#define ATT_SMEM 58880

__global__ __launch_bounds__(256) void attn_mma_k(const float* __restrict__ xq,
                                                  const __nv_bfloat16* __restrict__ xk,
                                                  const __nv_bfloat16* __restrict__ xv,
                                                  __nv_bfloat16* __restrict__ outb) {
    extern __shared__ char sm[];
    float*         q_s = (float*)sm;
    __nv_bfloat16* k_s = (__nv_bfloat16*)(sm + 17408);
    __nv_bfloat16* v_s = (__nv_bfloat16*)(sm + 38144);
    float*         S_s = (float*)sm;

    int tid = threadIdx.x;
    int bx = blockIdx.x, by = blockIdx.y, n = blockIdx.z;
    int y0 = by*8, x0 = bx*8;

    // load Q (fp32, 64 px)
    #pragma unroll
    for (int i = 0; i < 4; i++) {
        int idx = tid + 256*i;
        int row = idx >> 4, c4 = idx & 15;
        int yy = y0 + (row >> 3), xx = x0 + (row & 7);
        float4 val = ((const float4*)(xq + (((size_t)n << 14) + (yy << 7) + xx)*64))[c4];
        ((float4*)(q_s + row*QSP))[c4] = val;
    }
    // load K/V halo 12x12 (zero-padded)
    for (int idx = tid; idx < 144*8; idx += 256) {
        int hp = idx >> 3, c8 = idx & 7;
        int yy = y0 + (hp/12) - 2, xx = x0 + (hp%12) - 2;
        uint4 kv = make_uint4(0,0,0,0), vv = make_uint4(0,0,0,0);
        if (yy >= 0 && yy < 128 && xx >= 0 && xx < 128) {
            size_t base = (((size_t)n << 14) + (yy << 7) + xx) * 8;
            kv = ((const uint4*)xk)[base + c8];
            vv = ((const uint4*)xv)[base + c8];
        }
        ((uint4*)(k_s + hp*KSP))[c8] = kv;
        ((uint4*)(v_s + hp*KSP))[c8] = vv;
    }
    __syncthreads();

    int lane = tid & 31, w = tid >> 5;
    int lr = lane >> 2, lc = lane & 3;
    int wm = (w & 3)*16;

    // ---- stage A: S = Q @ K^T [64 x 144], tf32 hi/lo ----
    float cS[9][4];
    #pragma unroll
    for (int t2 = 0; t2 < 9; t2++)
        #pragma unroll
        for (int i = 0; i < 4; i++) cS[t2][i] = 0.f;
    {
        int sn0 = (w >> 2)*72;
        #pragma unroll
        for (int ki = 0; ki < 8; ki++) {
            int k0 = ki*8;
            float f0 = q_s[(wm+lr  )*QSP + k0 + lc    ];
            float f1 = q_s[(wm+lr+8)*QSP + k0 + lc    ];
            float f2 = q_s[(wm+lr  )*QSP + k0 + lc + 4];
            float f3 = q_s[(wm+lr+8)*QSP + k0 + lc + 4];
            unsigned h0,l0,h1,l1,h2,l2,h3,l3;
            tf32_split(f0, h0, l0); tf32_split(f1, h1, l1);
            tf32_split(f2, h2, l2); tf32_split(f3, h3, l3);
            #pragma unroll
            for (int t2 = 0; t2 < 9; t2++) {
                int row = sn0 + t2*8 + lr;
                unsigned b0 = bf2tf(k_s[row*KSP + k0 + lc    ]);
                unsigned b1 = bf2tf(k_s[row*KSP + k0 + lc + 4]);
                MMAT(cS[t2], h0,h1,h2,h3, b0,b1);
                MMAT(cS[t2], l0,l1,l2,l3, b0,b1);
            }
        }
    }
    __syncthreads();    // q_s/k_s dead; safe to overlay with S
    {
        int sn0 = (w >> 2)*72;
        #pragma unroll
        for (int t2 = 0; t2 < 9; t2++) {
            int col = sn0 + t2*8 + 2*lc;
            *(float2*)&S_s[(wm+lr  )*SSP + col] = make_float2(cS[t2][0], cS[t2][1]);
            *(float2*)&S_s[(wm+lr+8)*SSP + col] = make_float2(cS[t2][2], cS[t2][3]);
        }
    }
    __syncthreads();

    // ---- softmax fp32, in place S -> P (threads 0..63, one pixel each) ----
    if (tid < 64) {
        int py = tid >> 3, px = tid & 7;
        float v[25];
        float m = -1e30f;
        #pragma unroll
        for (int dy = 0; dy < 5; dy++)
            #pragma unroll
            for (int dx = 0; dx < 5; dx++) {
                float s = S_s[tid*SSP + (py+dy)*12 + (px+dx)];
                v[dy*5+dx] = s;
                m = fmaxf(m, s);
            }
        float ssum = 0.f;
        #pragma unroll
        for (int i = 0; i < 25; i++) { v[i] = __expf(v[i] - m); ssum += v[i]; }
        float inv = 1.f / ssum;
        float4* r4 = (float4*)(S_s + tid*SSP);
        float4 z = make_float4(0.f,0.f,0.f,0.f);
        #pragma unroll
        for (int i = 0; i < 37; i++) r4[i] = z;
        #pragma unroll
        for (int dy = 0; dy < 5; dy++)
            #pragma unroll
            for (int dx = 0; dx < 5; dx++)
                S_s[tid*SSP + (py+dy)*12 + (px+dx)] = v[dy*5+dx] * inv;
    }
    __syncthreads();

    // ---- PV: O = P @ V [64 x 64], tf32 hi/lo; B direct from v_s[hp][ch] ----
    {
        int wn = (w >> 2)*32;
        float cO[4][4];
        #pragma unroll
        for (int t2 = 0; t2 < 4; t2++)
            #pragma unroll
            for (int i = 0; i < 4; i++) cO[t2][i] = 0.f;
        #pragma unroll
        for (int ki = 0; ki < 18; ki++) {
            int k0 = ki*8;
            float f0 = S_s[(wm+lr  )*SSP + k0 + lc    ];
            float f1 = S_s[(wm+lr+8)*SSP + k0 + lc    ];
            float f2 = S_s[(wm+lr  )*SSP + k0 + lc + 4];
            float f3 = S_s[(wm+lr+8)*SSP + k0 + lc + 4];
            unsigned h0,l0,h1,l1,h2,l2,h3,l3;
            tf32_split(f0, h0, l0); tf32_split(f1, h1, l1);
            tf32_split(f2, h2, l2); tf32_split(f3, h3, l3);
            #pragma unroll
            for (int t2 = 0; t2 < 4; t2++) {
                int n0 = wn + t2*8;
                unsigned b0 = bf2tf(v_s[(k0 + lc    )*KSP + n0 + lr]);
                unsigned b1 = bf2tf(v_s[(k0 + lc + 4)*KSP + n0 + lr]);
                MMAT(cO[t2], h0,h1,h2,h3, b0,b1);
                MMAT(cO[t2], l0,l1,l2,l3, b0,b1);
            }
        }
        int p0 = wm + lr, p1 = p0 + 8;
        size_t g0 = (((size_t)n << 14) + ((size_t)(y0 + (p0>>3)) << 7) + (x0 + (p0&7)))*64;
        size_t g1 = (((size_t)n << 14) + ((size_t)(y0 + (p1>>3)) << 7) + (x0 + (p1&7)))*64;
        #pragma unroll
        for (int t2 = 0; t2 < 4; t2++) {
            int ch = wn + t2*8 + 2*lc;
            *(unsigned*)&outb[g0 + ch] = pack_bf(fmaxf(cO[t2][0],0.f), fmaxf(cO[t2][1],0.f));
            *(unsigned*)&outb[g1 + ch] = pack_bf(fmaxf(cO[t2][2],0.f), fmaxf(cO[t2][3],0.f));
        }
    }
}

// ---------------------------------------------------------------------------
// conv_out + residual: h NHWC bf16 -> conv3x3 (64->3) + x -> NCHW fp32.
// ---------------------------------------------------------------------------
#define COP 72

__global__ __launch_bounds__(256) void conv_out_k(const __nv_bfloat16* __restrict__ h,
                                                  const float* __restrict__ w,
                                                  const float* __restrict__ xin,
                                                  float* __restrict__ out) {
    extern __shared__ char smc[];
    float* ws = (float*)smc;                          // 1728 floats [tap][o][c]
    __nv_bfloat16* hs = (__nv_bfloat16*)(smc + 6912); // 324 x COP
    int tid = threadIdx.x;
    int bx = blockIdx.x, by = blockIdx.y, n = blockIdx.z;
    int y0 = by*16, x0 = bx*16;

    for (int idx = tid; idx < 1728; idx += 256) {
        int tap = idx / 192, r = idx % 192, o = r >> 6, c = r & 63;
        ws[idx] = w[(o*64 + c)*9 + tap];
    }
    for (int idx = tid; idx < 324*8; idx += 256) {
        int hp = idx >> 3, c8 = idx & 7;
        int yy = y0 + hp/18 - 1, xx = x0 + hp%18 - 1;
        uint4 val = make_uint4(0,0,0,0);
        if (yy >= 0 && yy < 128 && xx >= 0 && xx < 128)
            val = ((const uint4*)(h + (((size_t)n << 14) + (yy << 7) + xx)*64))[c8];
        ((uint4*)(hs + hp*COP))[c8] = val;
    }
    __syncthreads();

    int py = tid >> 4, px = tid & 15;
    float acc0 = 0.f, acc1 = 0.f, acc2 = 0.f;
    #pragma unroll
    for (int dy = 0; dy < 3; dy++)
        #pragma unroll
        for (int dx = 0; dx < 3; dx++) {
            int tap = dy*3 + dx;
            const __nv_bfloat16* hp = hs + ((py+dy)*18 + (px+dx))*COP;
            const float* wp = ws + tap*192;
            #pragma unroll
            for (int c8 = 0; c8 < 8; c8++) {
                uint4 hv = ((const uint4*)hp)[c8];
                float f[8] = { bflo(hv.x), bfhi(hv.x), bflo(hv.y), bfhi(hv.y),
                               bflo(hv.z), bfhi(hv.z), bflo(hv.w), bfhi(hv.w) };
                #pragma unroll
                for (int j = 0; j < 8; j++) {
                    int c = c8*8 + j;
                    acc0 = fmaf(f[j], wp[c      ], acc0);
                    acc1 = fmaf(f[j], wp[c +  64], acc1);
                    acc2 = fmaf(f[j], wp[c + 128], acc2);
                }
            }
        }

    int po = ((y0+py) << 7) + (x0+px);
    out[((n*3 + 0) << 14) + po] = acc0 + xin[((n*3 + 0) << 14) + po];
    out[((n*3 + 1) << 14) + po] = acc1 + xin[((n*3 + 1) << 14) + po];
    out[((n*3 + 2) << 14) + po] = acc2 + xin[((n*3 + 2) << 14) + po];
}

// ---------------------------------------------------------------------------
extern "C" void kernel_launch(void* const* d_in, const int* in_sizes, int n_in,
                              void* d_out, int out_size) {
    const float* x       = (const float*)d_in[0];
    const float* conv_in = (const float*)d_in[1];
    const float* W[9];
    for (int i = 0; i < 9; i++) W[i] = (const float*)d_in[2 + i];
    const float* conv_out = (const float*)d_in[11];
    float* out = (float*)d_out;

    __nv_bfloat16 *H0, *H1, *K, *V, *WB;
    float *Q;
    cudaGetSymbolAddress((void**)&H0, g_hb0);
    cudaGetSymbolAddress((void**)&H1, g_hb1);
    cudaGetSymbolAddress((void**)&Q,  g_q);
    cudaGetSymbolAddress((void**)&K,  g_kb);
    cudaGetSymbolAddress((void**)&V,  g_vb);
    cudaGetSymbolAddress((void**)&WB, g_wb);

    size_t co_smem = 6912 + (size_t)324*COP*sizeof(__nv_bfloat16);   // ~53.6 KB
    cudaFuncSetAttribute(conv_out_k, cudaFuncAttributeMaxDynamicSharedMemorySize, (int)co_smem);
    cudaFuncSetAttribute(attn_mma_k, cudaFuncAttributeMaxDynamicSharedMemorySize, ATT_SMEM);

    convert_w_k<<<48, 256>>>(W[0], W[1], W[2], WB);
    convert_w_k<<<48, 256>>>(W[3], W[4], W[5], WB + 192*64);
    convert_w_k<<<48, 256>>>(W[6], W[7], W[8], WB + 2*192*64);

    conv_in_k<<<dim3(8,8,8), 256>>>(x, conv_in, H0);

    dim3 agrid(16, 16, 8);
    // layer 0: H0 -> H1
    qkv_k<<<NPIX/64, 256>>>(H0, WB, Q, K, V);
    attn_mma_k<<<agrid, 256, ATT_SMEM>>>(Q, K, V, H1);
    // layer 1: H1 -> H0
    qkv_k<<<NPIX/64, 256>>>(H1, WB + 192*64, Q, K, V);
    attn_mma_k<<<agrid, 256, ATT_SMEM>>>(Q, K, V, H0);
    // layer 2: H0 -> H1
    qkv_k<<<NPIX/64, 256>>>(H0, WB + 2*192*64, Q, K, V);
    attn_mma_k<<<agrid, 256, ATT_SMEM>>>(Q, K, V, H1);

    conv_out_k<<<dim3(8,8,8), 256, co_smem>>>(H1, conv_out, x, out);
}

// round 10
// speedup vs baseline: 1.0012x; 1.0012x over previous
#include <cuda_runtime.h>
#include <cuda_bf16.h>

#define NPIX (8*128*128)   // 131072 pixels
#define CCH  64

// Scratch (device globals). Activations NHWC.
__device__ __nv_bfloat16 g_hb0[(size_t)NPIX*CCH];
__device__ __nv_bfloat16 g_hb1[(size_t)NPIX*CCH];
__device__ float g_q[(size_t)NPIX*CCH];
__device__ __nv_bfloat16 g_kb[(size_t)NPIX*CCH];
__device__ __nv_bfloat16 g_vb[(size_t)NPIX*CCH];
__device__ __nv_bfloat16 g_wb[3*192*64];   // pre-converted [w1;w2;w3], k contiguous

__device__ __forceinline__ unsigned pack_bf(float a, float b) {
    __nv_bfloat162 h = __floats2bfloat162_rn(a, b);
    return *reinterpret_cast<unsigned*>(&h);
}
__device__ __forceinline__ unsigned pack2h(__nv_bfloat16 a, __nv_bfloat16 b) {
    __nv_bfloat162 h = __halves2bfloat162(a, b);
    return *reinterpret_cast<unsigned*>(&h);
}
__device__ __forceinline__ void cp16(unsigned smem_dst, const void* gsrc) {
    asm volatile("cp.async.ca.shared.global [%0], [%1], 16;\n"
                 :: "r"(smem_dst), "l"(gsrc));
}
__device__ __forceinline__ float bflo(unsigned u) { return __uint_as_float(u << 16); }
__device__ __forceinline__ float bfhi(unsigned u) { return __uint_as_float(u & 0xffff0000u); }

#define MMA(c, a0,a1,a2,a3, b0,b1) \
    asm volatile("mma.sync.aligned.m16n8k16.row.col.f32.bf16.bf16.f32 " \
                 "{%0,%1,%2,%3}, {%4,%5,%6,%7}, {%8,%9}, {%0,%1,%2,%3};" \
                 : "+f"(c[0]), "+f"(c[1]), "+f"(c[2]), "+f"(c[3]) \
                 : "r"(a0), "r"(a1), "r"(a2), "r"(a3), "r"(b0), "r"(b1))

// ---------------------------------------------------------------------------
// weight convert: [64x64] fp32 x3 -> bf16 [192][64]
// ---------------------------------------------------------------------------
__global__ void convert_w_k(const float* __restrict__ w1, const float* __restrict__ w2,
                            const float* __restrict__ w3, __nv_bfloat16* __restrict__ dst) {
    int idx = blockIdx.x*256 + threadIdx.x;
    if (idx >= 192*64) return;
    float v = (idx < 4096) ? w1[idx] : (idx < 8192) ? w2[idx-4096] : w3[idx-8192];
    dst[idx] = __float2bfloat16(v);
}

// ---------------------------------------------------------------------------
// conv_in: x NCHW -> relu(conv3x3) -> NHWC bf16. 16x16 tile, 512 threads,
// 2 threads/pixel (32 outputs each). Weights [tap][o] broadcast float4.
// ---------------------------------------------------------------------------
__global__ __launch_bounds__(512) void conv_in_k(const float* __restrict__ x,
                                                 const float* __restrict__ w,
                                                 __nv_bfloat16* __restrict__ out) {
    __shared__ float ws2[27*64];           // [tap][o]
    __shared__ float xs[3][18][18];
    int tid = threadIdx.x;
    int bx = blockIdx.x, by = blockIdx.y, n = blockIdx.z;
    int y0 = by*16, x0 = bx*16;

    for (int idx = tid; idx < 1728; idx += 512) {
        int o = idx / 27, t = idx % 27;
        ws2[t*64 + o] = w[idx];
    }
    for (int idx = tid; idx < 972; idx += 512) {
        int c = idx / 324, r = idx % 324;
        int yy = y0 + r/18 - 1, xx = x0 + r%18 - 1;
        float v = 0.f;
        if (yy >= 0 && yy < 128 && xx >= 0 && xx < 128)
            v = x[((n*3 + c) << 14) + (yy << 7) + xx];
        xs[c][r/18][r%18] = v;
    }
    __syncthreads();

    int pixel = tid >> 1, half = tid & 1;
    int py = pixel >> 4, px = pixel & 15;
    float v[27];
    int t = 0;
    #pragma unroll
    for (int c = 0; c < 3; c++)
        #pragma unroll
        for (int dy = 0; dy < 3; dy++)
            #pragma unroll
            for (int dx = 0; dx < 3; dx++, t++)
                v[t] = xs[c][py+dy][px+dx];

    size_t obase = (((size_t)n << 14) + ((size_t)(y0+py) << 7) + (x0+px)) * 64;
    #pragma unroll
    for (int chh = 0; chh < 2; chh++) {
        int ch = half*2 + chh;
        float acc[16];
        #pragma unroll
        for (int j = 0; j < 16; j++) acc[j] = 0.f;
        #pragma unroll
        for (int tt = 0; tt < 27; tt++) {
            float xv = v[tt];
            const float4* wp = (const float4*)(ws2 + tt*64 + ch*16);
            float4 w0 = wp[0], w1 = wp[1], w2 = wp[2], w3 = wp[3];
            acc[0]  = fmaf(xv, w0.x, acc[0]);  acc[1]  = fmaf(xv, w0.y, acc[1]);
            acc[2]  = fmaf(xv, w0.z, acc[2]);  acc[3]  = fmaf(xv, w0.w, acc[3]);
            acc[4]  = fmaf(xv, w1.x, acc[4]);  acc[5]  = fmaf(xv, w1.y, acc[5]);
            acc[6]  = fmaf(xv, w1.z, acc[6]);  acc[7]  = fmaf(xv, w1.w, acc[7]);
            acc[8]  = fmaf(xv, w2.x, acc[8]);  acc[9]  = fmaf(xv, w2.y, acc[9]);
            acc[10] = fmaf(xv, w2.z, acc[10]); acc[11] = fmaf(xv, w2.w, acc[11]);
            acc[12] = fmaf(xv, w3.x, acc[12]); acc[13] = fmaf(xv, w3.y, acc[13]);
            acc[14] = fmaf(xv, w3.z, acc[14]); acc[15] = fmaf(xv, w3.w, acc[15]);
        }
        uint4 u0 = make_uint4(pack_bf(fmaxf(acc[0],0.f),  fmaxf(acc[1],0.f)),
                              pack_bf(fmaxf(acc[2],0.f),  fmaxf(acc[3],0.f)),
                              pack_bf(fmaxf(acc[4],0.f),  fmaxf(acc[5],0.f)),
                              pack_bf(fmaxf(acc[6],0.f),  fmaxf(acc[7],0.f)));
        uint4 u1 = make_uint4(pack_bf(fmaxf(acc[8],0.f),  fmaxf(acc[9],0.f)),
                              pack_bf(fmaxf(acc[10],0.f), fmaxf(acc[11],0.f)),
                              pack_bf(fmaxf(acc[12],0.f), fmaxf(acc[13],0.f)),
                              pack_bf(fmaxf(acc[14],0.f), fmaxf(acc[15],0.f)));
        ((uint4*)(out + obase + ch*16))[0] = u0;
        ((uint4*)(out + obase + ch*16))[1] = u1;
    }
}

// ---------------------------------------------------------------------------
// qkv: fused triple 1x1 via bf16 mma (unchanged, proven)
// ---------------------------------------------------------------------------
__global__ __launch_bounds__(256) void qkv_k(const __nv_bfloat16* __restrict__ in,
                                             const __nv_bfloat16* __restrict__ wb,
                                             float* __restrict__ qo,
                                             __nv_bfloat16* __restrict__ ko,
                                             __nv_bfloat16* __restrict__ vo) {
    __shared__ __nv_bfloat16 a_s[64*72];
    __shared__ __nv_bfloat16 w_s[192*72];
    int tid = threadIdx.x;
    size_t pix0 = (size_t)blockIdx.x * 64;

    unsigned a_base = (unsigned)__cvta_generic_to_shared(a_s);
    unsigned w_base = (unsigned)__cvta_generic_to_shared(w_s);

    #pragma unroll
    for (int i = 0; i < 2; i++) {
        int idx = tid + 256*i;
        int row = idx >> 3, c8 = idx & 7;
        cp16(a_base + row*144 + c8*16, in + pix0*64 + (size_t)idx*8);
    }
    #pragma unroll
    for (int i = 0; i < 6; i++) {
        int idx = tid + 256*i;
        int row = idx >> 3, c8 = idx & 7;
        cp16(w_base + row*144 + c8*16, wb + row*64 + c8*8);
    }
    asm volatile("cp.async.commit_group;\n" ::: "memory");
    asm volatile("cp.async.wait_group 0;\n" ::: "memory");
    __syncthreads();

    int lane = tid & 31, w = tid >> 5;
    int wm = (w >> 1) * 16;
    int wn = (w & 1) * 96;
    int lr = lane >> 2, lc = lane & 3;

    float c[12][4];
    #pragma unroll
    for (int t = 0; t < 12; t++)
        #pragma unroll
        for (int i = 0; i < 4; i++) c[t][i] = 0.f;

    #pragma unroll
    for (int ks = 0; ks < 4; ks++) {
        int k0 = ks*16;
        unsigned a0 = *(const unsigned*)&a_s[(wm+lr  )*72 + k0 + lc*2    ];
        unsigned a1 = *(const unsigned*)&a_s[(wm+lr+8)*72 + k0 + lc*2    ];
        unsigned a2 = *(const unsigned*)&a_s[(wm+lr  )*72 + k0 + lc*2 + 8];
        unsigned a3 = *(const unsigned*)&a_s[(wm+lr+8)*72 + k0 + lc*2 + 8];
        #pragma unroll
        for (int t = 0; t < 12; t++) {
            int bc = wn + t*8 + lr;
            unsigned b0 = *(const unsigned*)&w_s[bc*72 + k0 + lc*2    ];
            unsigned b1 = *(const unsigned*)&w_s[bc*72 + k0 + lc*2 + 8];
            MMA(c[t], a0,a1,a2,a3, b0,b1);
        }
    }

    size_t pixA = pix0 + wm + lr;
    size_t pixB = pixA + 8;
    #pragma unroll
    for (int t = 0; t < 12; t++) {
        int n0 = wn + t*8 + lc*2;
        if (n0 < 64) {
            *(float2*)(qo + pixA*64 + n0) = make_float2(c[t][0], c[t][1]);
            *(float2*)(qo + pixB*64 + n0) = make_float2(c[t][2], c[t][3]);
        } else if (n0 < 128) {
            *(unsigned*)(ko + pixA*64 + n0 - 64) = pack_bf(c[t][0], c[t][1]);
            *(unsigned*)(ko + pixB*64 + n0 - 64) = pack_bf(c[t][2], c[t][3]);
        } else {
            *(unsigned*)(vo + pixA*64 + n0 - 128) = pack_bf(c[t][0], c[t][1]);
            *(unsigned*)(vo + pixB*64 + n0 - 128) = pack_bf(c[t][2], c[t][3]);
        }
    }
}

// ---------------------------------------------------------------------------
// attn via bf16 tensor cores, hi/lo-split Q and P (fp32-class precision).
// Per 8x8 tile: load Q(split)/K/V(transposed) -> S = (Qhi+Qlo)K^T (bf16 mma)
// -> fp32 softmax -> P split hi/lo -> O = (Phi+Plo)V (bf16 mma) -> relu.
// ---------------------------------------------------------------------------
#define AQP 72     // bf16 stride: q_hi/q_lo
#define AKP 72     // bf16 stride: k_s
#define AVP 152    // bf16 stride: v_t (64 rows x 144 used + pad)
#define APP 152    // bf16 stride: P_hi/P_lo
#define ASS 148    // fp32 stride: S
// smem bytes: q_hi 0 | q_lo 9216 | k_s 18432..39168 | S overlays 0..37888
//             v_t 39168..58624 | P_hi 58624..78080 | P_lo 78080..97536
#define ATT_SMEM 97536

__global__ __launch_bounds__(256) void attn_mma_k(const float* __restrict__ xq,
                                                  const __nv_bfloat16* __restrict__ xk,
                                                  const __nv_bfloat16* __restrict__ xv,
                                                  __nv_bfloat16* __restrict__ outb) {
    extern __shared__ char sm[];
    __nv_bfloat16* q_hi = (__nv_bfloat16*)sm;
    __nv_bfloat16* q_lo = (__nv_bfloat16*)(sm + 9216);
    __nv_bfloat16* k_s  = (__nv_bfloat16*)(sm + 18432);
    float*         S_s  = (float*)sm;
    __nv_bfloat16* v_t  = (__nv_bfloat16*)(sm + 39168);
    __nv_bfloat16* P_hi = (__nv_bfloat16*)(sm + 58624);
    __nv_bfloat16* P_lo = (__nv_bfloat16*)(sm + 78080);

    int tid = threadIdx.x;
    int bx = blockIdx.x, by = blockIdx.y, n = blockIdx.z;
    int y0 = by*8, x0 = bx*8;

    // Q: load fp32, split hi/lo bf16
    #pragma unroll
    for (int i = 0; i < 4; i++) {
        int idx = tid + 256*i;
        int row = idx >> 4, c4 = idx & 15;
        int yy = y0 + (row >> 3), xx = x0 + (row & 7);
        float4 v = ((const float4*)(xq + (((size_t)n << 14) + (yy << 7) + xx)*64))[c4];
        __nv_bfloat16 hx = __float2bfloat16(v.x), hy = __float2bfloat16(v.y);
        __nv_bfloat16 hz = __float2bfloat16(v.z), hw = __float2bfloat16(v.w);
        __nv_bfloat16 lx = __float2bfloat16(v.x - __bfloat162float(hx));
        __nv_bfloat16 ly = __float2bfloat16(v.y - __bfloat162float(hy));
        __nv_bfloat16 lz = __float2bfloat16(v.z - __bfloat162float(hz));
        __nv_bfloat16 lw = __float2bfloat16(v.w - __bfloat162float(hw));
        *(uint2*)(q_hi + row*AQP + c4*4) = make_uint2(pack2h(hx,hy), pack2h(hz,hw));
        *(uint2*)(q_lo + row*AQP + c4*4) = make_uint2(pack2h(lx,ly), pack2h(lz,lw));
    }
    // K: straight copy; V: transpose to v_t[ch][hp] during load (zero-padded)
    for (int idx = tid; idx < 144*8; idx += 256) {
        int hp = idx >> 3, c8 = idx & 7;
        int yy = y0 + (hp/12) - 2, xx = x0 + (hp%12) - 2;
        uint4 kv = make_uint4(0,0,0,0), vv = make_uint4(0,0,0,0);
        if (yy >= 0 && yy < 128 && xx >= 0 && xx < 128) {
            size_t base = (((size_t)n << 14) + (yy << 7) + xx) * 8;
            kv = ((const uint4*)xk)[base + c8];
            vv = ((const uint4*)xv)[base + c8];
        }
        ((uint4*)(k_s + hp*AKP))[c8] = kv;
        const __nv_bfloat16* vb = (const __nv_bfloat16*)&vv;
        #pragma unroll
        for (int j = 0; j < 8; j++)
            v_t[(c8*8 + j)*AVP + hp] = vb[j];
    }
    // zero v_t pad columns 144..151 (avoid NaN garbage in PV)
    if (tid < 64) ((uint4*)(v_t + tid*AVP + 144))[0] = make_uint4(0,0,0,0);
    __syncthreads();

    int lane = tid & 31, w = tid >> 5;
    int lr = lane >> 2, lc = lane & 3;
    int wm = (w & 3)*16;
    int sn0 = (w >> 2)*72;

    // ---- stage A: S = (Qhi + Qlo) @ K^T [64 x 144] ----
    float cS[9][4];
    #pragma unroll
    for (int t2 = 0; t2 < 9; t2++)
        #pragma unroll
        for (int i = 0; i < 4; i++) cS[t2][i] = 0.f;
    #pragma unroll
    for (int ks = 0; ks < 4; ks++) {
        int k0 = ks*16;
        unsigned ah0 = *(const unsigned*)&q_hi[(wm+lr  )*AQP + k0 + 2*lc    ];
        unsigned ah1 = *(const unsigned*)&q_hi[(wm+lr+8)*AQP + k0 + 2*lc    ];
        unsigned ah2 = *(const unsigned*)&q_hi[(wm+lr  )*AQP + k0 + 2*lc + 8];
        unsigned ah3 = *(const unsigned*)&q_hi[(wm+lr+8)*AQP + k0 + 2*lc + 8];
        unsigned al0 = *(const unsigned*)&q_lo[(wm+lr  )*AQP + k0 + 2*lc    ];
        unsigned al1 = *(const unsigned*)&q_lo[(wm+lr+8)*AQP + k0 + 2*lc    ];
        unsigned al2 = *(const unsigned*)&q_lo[(wm+lr  )*AQP + k0 + 2*lc + 8];
        unsigned al3 = *(const unsigned*)&q_lo[(wm+lr+8)*AQP + k0 + 2*lc + 8];
        #pragma unroll
        for (int t2 = 0; t2 < 9; t2++) {
            int row = sn0 + t2*8 + lr;
            unsigned b0 = *(const unsigned*)&k_s[row*AKP + k0 + 2*lc    ];
            unsigned b1 = *(const unsigned*)&k_s[row*AKP + k0 + 2*lc + 8];
            MMA(cS[t2], ah0,ah1,ah2,ah3, b0,b1);
            MMA(cS[t2], al0,al1,al2,al3, b0,b1);
        }
    }
    __syncthreads();    // q/k dead; overlay with S
    #pragma unroll
    for (int t2 = 0; t2 < 9; t2++) {
        int col = sn0 + t2*8 + 2*lc;
        *(float2*)&S_s[(wm+lr  )*ASS + col] = make_float2(cS[t2][0], cS[t2][1]);
        *(float2*)&S_s[(wm+lr+8)*ASS + col] = make_float2(cS[t2][2], cS[t2][3]);
    }
    __syncthreads();

    // ---- softmax fp32 (threads 0..63); write P hi/lo with zeroed rows ----
    if (tid < 64) {
        int py = tid >> 3, px = tid & 7;
        float v[25];
        float m = -1e30f;
        #pragma unroll
        for (int dy = 0; dy < 5; dy++)
            #pragma unroll
            for (int dx = 0; dx < 5; dx++) {
                float s = S_s[tid*ASS + (py+dy)*12 + (px+dx)];
                v[dy*5+dx] = s;
                m = fmaxf(m, s);
            }
        float ssum = 0.f;
        #pragma unroll
        for (int i = 0; i < 25; i++) { v[i] = __expf(v[i] - m); ssum += v[i]; }
        float inv = 1.f / ssum;
        uint4 z = make_uint4(0,0,0,0);
        uint4* ph4 = (uint4*)(P_hi + tid*APP);
        uint4* pl4 = (uint4*)(P_lo + tid*APP);
        #pragma unroll
        for (int i = 0; i < 19; i++) { ph4[i] = z; pl4[i] = z; }
        #pragma unroll
        for (int dy = 0; dy < 5; dy++)
            #pragma unroll
            for (int dx = 0; dx < 5; dx++) {
                float wv = v[dy*5+dx] * inv;
                __nv_bfloat16 hh = __float2bfloat16(wv);
                __nv_bfloat16 ll = __float2bfloat16(wv - __bfloat162float(hh));
                P_hi[tid*APP + (py+dy)*12 + (px+dx)] = hh;
                P_lo[tid*APP + (py+dy)*12 + (px+dx)] = ll;
            }
    }
    __syncthreads();

    // ---- PV: O = (Phi + Plo) @ V [64 x 64], relu, bf16 out ----
    {
        int wn = (w >> 2)*32;
        float cO[4][4];
        #pragma unroll
        for (int t2 = 0; t2 < 4; t2++)
            #pragma unroll
            for (int i = 0; i < 4; i++) cO[t2][i] = 0.f;
        #pragma unroll
        for (int ki = 0; ki < 9; ki++) {
            int k0 = ki*16;
            unsigned ah0 = *(const unsigned*)&P_hi[(wm+lr  )*APP + k0 + 2*lc    ];
            unsigned ah1 = *(const unsigned*)&P_hi[(wm+lr+8)*APP + k0 + 2*lc    ];
            unsigned ah2 = *(const unsigned*)&P_hi[(wm+lr  )*APP + k0 + 2*lc + 8];
            unsigned ah3 = *(const unsigned*)&P_hi[(wm+lr+8)*APP + k0 + 2*lc + 8];
            unsigned al0 = *(const unsigned*)&P_lo[(wm+lr  )*APP + k0 + 2*lc    ];
            unsigned al1 = *(const unsigned*)&P_lo[(wm+lr+8)*APP + k0 + 2*lc    ];
            unsigned al2 = *(const unsigned*)&P_lo[(wm+lr  )*APP + k0 + 2*lc + 8];
            unsigned al3 = *(const unsigned*)&P_lo[(wm+lr+8)*APP + k0 + 2*lc + 8];
            #pragma unroll
            for (int t2 = 0; t2 < 4; t2++) {
                int row = wn + t2*8 + lr;     // ch row of v_t
                unsigned b0 = *(const unsigned*)&v_t[row*AVP + k0 + 2*lc    ];
                unsigned b1 = *(const unsigned*)&v_t[row*AVP + k0 + 2*lc + 8];
                MMA(cO[t2], ah0,ah1,ah2,ah3, b0,b1);
                MMA(cO[t2], al0,al1,al2,al3, b0,b1);
            }
        }
        int p0 = wm + lr, p1 = p0 + 8;
        size_t g0 = (((size_t)n << 14) + ((size_t)(y0 + (p0>>3)) << 7) + (x0 + (p0&7)))*64;
        size_t g1 = (((size_t)n << 14) + ((size_t)(y0 + (p1>>3)) << 7) + (x0 + (p1&7)))*64;
        #pragma unroll
        for (int t2 = 0; t2 < 4; t2++) {
            int wn2 = (w >> 2)*32;
            int ch = wn2 + t2*8 + 2*lc;
            *(unsigned*)&outb[g0 + ch] = pack_bf(fmaxf(cO[t2][0],0.f), fmaxf(cO[t2][1],0.f));
            *(unsigned*)&outb[g1 + ch] = pack_bf(fmaxf(cO[t2][2],0.f), fmaxf(cO[t2][3],0.f));
        }
    }
}

// ---------------------------------------------------------------------------
// conv_out + residual: h NHWC bf16 -> conv3x3 (64->3) + x -> NCHW fp32.
// ---------------------------------------------------------------------------
#define COP 72

__global__ __launch_bounds__(256) void conv_out_k(const __nv_bfloat16* __restrict__ h,
                                                  const float* __restrict__ w,
                                                  const float* __restrict__ xin,
                                                  float* __restrict__ out) {
    extern __shared__ char smc[];
    float* ws = (float*)smc;                          // 1728 floats [tap][o][c]
    __nv_bfloat16* hs = (__nv_bfloat16*)(smc + 6912); // 324 x COP
    int tid = threadIdx.x;
    int bx = blockIdx.x, by = blockIdx.y, n = blockIdx.z;
    int y0 = by*16, x0 = bx*16;

    for (int idx = tid; idx < 1728; idx += 256) {
        int tap = idx / 192, r = idx % 192, o = r >> 6, c = r & 63;
        ws[idx] = w[(o*64 + c)*9 + tap];
    }
    for (int idx = tid; idx < 324*8; idx += 256) {
        int hp = idx >> 3, c8 = idx & 7;
        int yy = y0 + hp/18 - 1, xx = x0 + hp%18 - 1;
        uint4 val = make_uint4(0,0,0,0);
        if (yy >= 0 && yy < 128 && xx >= 0 && xx < 128)
            val = ((const uint4*)(h + (((size_t)n << 14) + (yy << 7) + xx)*64))[c8];
        ((uint4*)(hs + hp*COP))[c8] = val;
    }
    __syncthreads();

    int py = tid >> 4, px = tid & 15;
    float acc0 = 0.f, acc1 = 0.f, acc2 = 0.f;
    #pragma unroll
    for (int dy = 0; dy < 3; dy++)
        #pragma unroll
        for (int dx = 0; dx < 3; dx++) {
            int tap = dy*3 + dx;
            const __nv_bfloat16* hp = hs + ((py+dy)*18 + (px+dx))*COP;
            const float* wp = ws + tap*192;
            #pragma unroll
            for (int c8 = 0; c8 < 8; c8++) {
                uint4 hv = ((const uint4*)hp)[c8];
                float f[8] = { bflo(hv.x), bfhi(hv.x), bflo(hv.y), bfhi(hv.y),
                               bflo(hv.z), bfhi(hv.z), bflo(hv.w), bfhi(hv.w) };
                #pragma unroll
                for (int j = 0; j < 8; j++) {
                    int c = c8*8 + j;
                    acc0 = fmaf(f[j], wp[c      ], acc0);
                    acc1 = fmaf(f[j], wp[c +  64], acc1);
                    acc2 = fmaf(f[j], wp[c + 128], acc2);
                }
            }
        }

    int po = ((y0+py) << 7) + (x0+px);
    out[((n*3 + 0) << 14) + po] = acc0 + xin[((n*3 + 0) << 14) + po];
    out[((n*3 + 1) << 14) + po] = acc1 + xin[((n*3 + 1) << 14) + po];
    out[((n*3 + 2) << 14) + po] = acc2 + xin[((n*3 + 2) << 14) + po];
}

// ---------------------------------------------------------------------------
extern "C" void kernel_launch(void* const* d_in, const int* in_sizes, int n_in,
                              void* d_out, int out_size) {
    const float* x       = (const float*)d_in[0];
    const float* conv_in = (const float*)d_in[1];
    const float* W[9];
    for (int i = 0; i < 9; i++) W[i] = (const float*)d_in[2 + i];
    const float* conv_out = (const float*)d_in[11];
    float* out = (float*)d_out;

    __nv_bfloat16 *H0, *H1, *K, *V, *WB;
    float *Q;
    cudaGetSymbolAddress((void**)&H0, g_hb0);
    cudaGetSymbolAddress((void**)&H1, g_hb1);
    cudaGetSymbolAddress((void**)&Q,  g_q);
    cudaGetSymbolAddress((void**)&K,  g_kb);
    cudaGetSymbolAddress((void**)&V,  g_vb);
    cudaGetSymbolAddress((void**)&WB, g_wb);

    size_t co_smem = 6912 + (size_t)324*COP*sizeof(__nv_bfloat16);   // ~53.6 KB
    cudaFuncSetAttribute(conv_out_k, cudaFuncAttributeMaxDynamicSharedMemorySize, (int)co_smem);
    cudaFuncSetAttribute(attn_mma_k, cudaFuncAttributeMaxDynamicSharedMemorySize, ATT_SMEM);

    convert_w_k<<<48, 256>>>(W[0], W[1], W[2], WB);
    convert_w_k<<<48, 256>>>(W[3], W[4], W[5], WB + 192*64);
    convert_w_k<<<48, 256>>>(W[6], W[7], W[8], WB + 2*192*64);

    conv_in_k<<<dim3(8,8,8), 512>>>(x, conv_in, H0);

    dim3 agrid(16, 16, 8);
    // layer 0: H0 -> H1
    qkv_k<<<NPIX/64, 256>>>(H0, WB, Q, K, V);
    attn_mma_k<<<agrid, 256, ATT_SMEM>>>(Q, K, V, H1);
    // layer 1: H1 -> H0
    qkv_k<<<NPIX/64, 256>>>(H1, WB + 192*64, Q, K, V);
    attn_mma_k<<<agrid, 256, ATT_SMEM>>>(Q, K, V, H0);
    // layer 2: H0 -> H1
    qkv_k<<<NPIX/64, 256>>>(H0, WB + 2*192*64, Q, K, V);
    attn_mma_k<<<agrid, 256, ATT_SMEM>>>(Q, K, V, H1);

    conv_out_k<<<dim3(8,8,8), 256, co_smem>>>(H1, conv_out, x, out);
}